// round 15
// baseline (speedup 1.0000x reference)
#include <cuda_runtime.h>
#include <cuda_fp16.h>
#include <cstdint>

#define BATCH  4
#define SEQ    1024
#define DM     1024
#define NHEAD  16
#define DEPTH  64
#define MROWS  (BATCH * SEQ)
#define NX (MROWS * DM)
#define NW (DM * DM)

// ---------------- scratch (device globals; allocation-free rule) ------------
__device__ __half g_Qh[(size_t)MROWS * DM];
__device__ __half g_Kh[(size_t)MROWS * DM];
__device__ __half g_Vh[(size_t)MROWS * DM];
__device__ __half g_Oh[(size_t)MROWS * DM];
__device__ __half g_xq[(size_t)NX];
__device__ __half g_xk[(size_t)NX];
__device__ __half g_xv[(size_t)NX];
__device__ __half g_wq[(size_t)NW];
__device__ __half g_wk[(size_t)NW];
__device__ __half g_wv[(size_t)NW];
__device__ __half g_wp[(size_t)NW];

// ---------------- helpers ----------------------------------------------------
__device__ __forceinline__ uint32_t smem_u32(const void* p) {
    uint32_t a;
    asm("{ .reg .u64 t; cvta.to.shared.u64 t, %1; cvt.u32.u64 %0, t; }"
        : "=r"(a) : "l"(p));
    return a;
}
__device__ __forceinline__ void ldm_x4(uint32_t* r, uint32_t addr) {
    asm volatile("ldmatrix.sync.aligned.m8n8.x4.shared.b16 {%0,%1,%2,%3}, [%4];"
                 : "=r"(r[0]), "=r"(r[1]), "=r"(r[2]), "=r"(r[3]) : "r"(addr));
}
__device__ __forceinline__ void ldm_x4_t(uint32_t* r, uint32_t addr) {
    asm volatile("ldmatrix.sync.aligned.m8n8.x4.trans.shared.b16 {%0,%1,%2,%3}, [%4];"
                 : "=r"(r[0]), "=r"(r[1]), "=r"(r[2]), "=r"(r[3]) : "r"(addr));
}
__device__ __forceinline__ void mma16816(float* d, const uint32_t* a,
                                         const uint32_t* b) {
    asm("mma.sync.aligned.m16n8k16.row.col.f32.f16.f16.f32 "
        "{%0,%1,%2,%3}, {%4,%5,%6,%7}, {%8,%9}, {%0,%1,%2,%3};"
        : "+f"(d[0]), "+f"(d[1]), "+f"(d[2]), "+f"(d[3])
        : "r"(a[0]), "r"(a[1]), "r"(a[2]), "r"(a[3]), "r"(b[0]), "r"(b[1]));
}
__device__ __forceinline__ uint32_t packh2(float a, float b) {
    __half2 h = __floats2half2_rn(a, b);
    return *(uint32_t*)&h;
}
#define CP_ASYNC16(saddr, gptr) \
    asm volatile("cp.async.cg.shared.global [%0], [%1], 16;" \
                 :: "r"(saddr), "l"(gptr))
#define CP_COMMIT() asm volatile("cp.async.commit_group;")
#define CP_WAIT1()  asm volatile("cp.async.wait_group 1;")
#define CP_WAIT0()  asm volatile("cp.async.wait_group 0;")

// ---------------- single mega-conv: all 7 fp32->fp16 tensors -----------------
__global__ __launch_bounds__(256)
void conv_all(const float* __restrict__ q, const float* __restrict__ k,
              const float* __restrict__ v, const float* __restrict__ wq,
              const float* __restrict__ wk, const float* __restrict__ wv,
              const float* __restrict__ wp,
              __half* __restrict__ xq, __half* __restrict__ xk,
              __half* __restrict__ xv, __half* __restrict__ dwq,
              __half* __restrict__ dwk, __half* __restrict__ dwv,
              __half* __restrict__ dwp)
{
    const float* src; __half* dst; int n;
    switch (blockIdx.y) {
        case 0:  src = q;  dst = xq;  n = NX; break;
        case 1:  src = k;  dst = xk;  n = NX; break;
        case 2:  src = v;  dst = xv;  n = NX; break;
        case 3:  src = wq; dst = dwq; n = NW; break;
        case 4:  src = wk; dst = dwk; n = NW; break;
        case 5:  src = wv; dst = dwv; n = NW; break;
        default: src = wp; dst = dwp; n = NW; break;
    }
    int i = (blockIdx.x * 256 + threadIdx.x) * 8;
    if (i >= n) return;
    float4 v0 = *(const float4*)(src + i);
    float4 v1 = *(const float4*)(src + i + 4);
    __half h[8] = {__float2half_rn(v0.x), __float2half_rn(v0.y),
                   __float2half_rn(v0.z), __float2half_rn(v0.w),
                   __float2half_rn(v1.x), __float2half_rn(v1.y),
                   __float2half_rn(v1.z), __float2half_rn(v1.w)};
    *(uint4*)(dst + i) = *(uint4*)h;
}

// ---------------- 1-pass HMMA GEMM core, 3-stage pipeline, LDSM prefetch ----
#define BM 128
#define BN 128
#define BKG 32
#define SKPG 40
#define GT_H (128 * SKPG)            // 5120 halves per tile
#define GSTAGE_H (2 * GT_H)          // A, W
#define GEMM_SMEM (3 * GSTAGE_H * 2) // 61440 bytes

__device__ __forceinline__ void gemm_issue(uint32_t sb, int buf, int k0,
    const __half* A0, const __half* W0, int t)
{
    const __half* bases[2] = {A0, W0};
    const uint32_t stb = sb + buf * (GSTAGE_H * 2);
    #pragma unroll
    for (int j = 0; j < 4; j++) {
        const int tile = j >> 1;
        const int r = t + (j & 1) * 256;   // 0..511
        const int row = r >> 2, c16 = r & 3;
        const __half* gp = bases[tile] + (size_t)row * DM + k0 + c16 * 8;
        uint32_t sa = stb + (tile * GT_H + row * SKPG + c16 * 8) * 2;
        CP_ASYNC16(sa, gp);
    }
    CP_COMMIT();
}

__device__ __forceinline__ void gemm_core(
    const __half* __restrict__ Ahi, const __half* __restrict__ Whi,
    const float* __restrict__ bias,
    float* __restrict__ Cf, __half* __restrict__ Chi, float scale)
{
    extern __shared__ __half sh[];
    const uint32_t sb = smem_u32(sh);

    const int t      = threadIdx.x;
    const int lane   = t & 31;
    const int wid    = t >> 5;
    const int warp_m = wid & 3;
    const int warp_n = wid >> 2;
    const int sub    = lane >> 3;
    const int l7     = lane & 7;
    const int bm     = blockIdx.y * BM;
    const int bn     = blockIdx.x * BN;

    const __half* A0 = Ahi + (size_t)bm * DM;
    const __half* W0 = Whi + (size_t)bn * DM;

    float acc[2][8][4];
    #pragma unroll
    for (int i = 0; i < 2; i++)
        #pragma unroll
        for (int j = 0; j < 8; j++)
            #pragma unroll
            for (int c = 0; c < 4; c++) acc[i][j][c] = 0.f;

    const uint32_t a_off =
        ((warp_m * 32 + (l7 | ((sub & 1) << 3))) * SKPG + ((sub >> 1) << 3)) * 2;
    const uint32_t b_off =
        ((warp_n * 64 + (l7 + ((sub >> 1) << 3))) * SKPG + ((sub & 1) << 3)) * 2;

    gemm_issue(sb, 0, 0, A0, W0, t);
    gemm_issue(sb, 1, BKG, A0, W0, t);

    const int NS = DM / BKG;   // 32
    for (int kc = 0; kc < NS; kc++) {
        if (kc + 1 < NS) CP_WAIT1(); else CP_WAIT0();
        __syncthreads();
        if (kc + 2 < NS)
            gemm_issue(sb, (kc + 2) % 3, (kc + 2) * BKG, A0, W0, t);

        const uint32_t bA = sb + (kc % 3) * (GSTAGE_H * 2);
        const uint32_t bW = bA + GT_H * 2;

        // A fragments for both k16 steps up front
        uint32_t ah[2][2][4];
        #pragma unroll
        for (int k16 = 0; k16 < 2; k16++)
            #pragma unroll
            for (int im = 0; im < 2; im++)
                ldm_x4(ah[k16][im],
                       bA + a_off + im * (16 * SKPG * 2) + k16 * 32);

        // B fragments: one-deep prefetch across 8 (k16,jn16) groups
        uint32_t rh[2][4];
        ldm_x4(rh[0], bW + b_off);           // g=0: k16=0, jn16=0
        #pragma unroll
        for (int gидx = 0; gидx < 8; gидx++) {
            const int k16 = gидx >> 2, jn = gидx & 3;
            const int cur = gидx & 1;
            if (gидx < 7) {
                const int gn = gидx + 1;
                ldm_x4(rh[cur ^ 1], bW + b_off + (gn & 3) * (16 * SKPG * 2)
                                     + (gn >> 2) * 32);
            }
            mma16816(acc[0][jn * 2],     ah[k16][0], rh[cur]);
            mma16816(acc[1][jn * 2],     ah[k16][1], rh[cur]);
            mma16816(acc[0][jn * 2 + 1], ah[k16][0], rh[cur] + 2);
            mma16816(acc[1][jn * 2 + 1], ah[k16][1], rh[cur] + 2);
        }
    }

    const int g  = lane >> 2;
    const int tc = (lane & 3) * 2;
    #pragma unroll
    for (int im = 0; im < 2; im++) {
        const int r0 = bm + warp_m * 32 + im * 16 + g;
        #pragma unroll
        for (int jn = 0; jn < 8; jn++) {
            const int c = bn + warp_n * 64 + jn * 8 + tc;
            const float b0 = bias[c], b1 = bias[c + 1];
            float v0 = (acc[im][jn][0] + b0) * scale;
            float v1 = (acc[im][jn][1] + b1) * scale;
            float v2 = (acc[im][jn][2] + b0) * scale;
            float v3 = (acc[im][jn][3] + b1) * scale;
            if (Cf) {
                *(float2*)(Cf + (size_t)r0 * DM + c) = make_float2(v0, v1);
                *(float2*)(Cf + (size_t)(r0 + 8) * DM + c) = make_float2(v2, v3);
            } else {
                *(uint32_t*)(Chi + (size_t)r0 * DM + c) = packh2(v0, v1);
                *(uint32_t*)(Chi + (size_t)(r0 + 8) * DM + c) = packh2(v2, v3);
            }
        }
    }
}

// batched Q/K/V projections in one launch (blockIdx.z selects)
__global__ void __launch_bounds__(256, 2)
gemm_qkv(const __half* __restrict__ xq, const __half* __restrict__ xk,
         const __half* __restrict__ xv, const __half* __restrict__ wq,
         const __half* __restrict__ wk, const __half* __restrict__ wv,
         const float* __restrict__ bq, const float* __restrict__ bk,
         const float* __restrict__ bv,
         __half* __restrict__ Qh, __half* __restrict__ Kh,
         __half* __restrict__ Vh)
{
    const int z = blockIdx.z;
    const __half* A = (z == 0) ? xq : (z == 1) ? xk : xv;
    const __half* W = (z == 0) ? wq : (z == 1) ? wk : wv;
    const float*  b = (z == 0) ? bq : (z == 1) ? bk : bv;
    __half*       C = (z == 0) ? Qh : (z == 1) ? Kh : Vh;
    const float   s = (z == 0) ? 0.125f : 1.0f;
    gemm_core(A, W, b, nullptr, C, s);
}

// single GEMM (output projection, fp32 out)
__global__ void __launch_bounds__(256, 2)
gemm_out(const __half* __restrict__ A, const __half* __restrict__ W,
         const float* __restrict__ bias, float* __restrict__ Cf)
{
    gemm_core(A, W, bias, Cf, nullptr, 1.0f);
}

// ---------------- HMMA flash attention, LDSM prefetch, 3-stage pipeline -----
#define ATK  64
#define ASKP 72
#define AT_H (64 * ASKP)
#define ASTAGE_H (2 * AT_H)
#define ATTN_SMEM (3 * ASTAGE_H * 2)   // 55296 bytes

__device__ __forceinline__ void attn_issue(uint32_t sb, int buf, int k0,
    const __half* Khb, const __half* Vhb, int t)
{
    const uint32_t stb = sb + buf * (ASTAGE_H * 2);
    #pragma unroll
    for (int j = 0; j < 4; j++) {
        const int tile = j >> 1;           // 0=Kh, 1=Vh
        const int r = t + (j & 1) * 256;
        const int row = r >> 3, c16 = r & 7;
        const __half* gp = (tile ? Vhb : Khb) + (size_t)(k0 + row) * DM
                           + c16 * 8;
        uint32_t sa = stb + (tile * AT_H + row * ASKP + c16 * 8) * 2;
        CP_ASYNC16(sa, gp);
    }
    CP_COMMIT();
}

__global__ void __launch_bounds__(256, 2)
attn_mma(const float* __restrict__ mask)
{
    extern __shared__ __half sh[];
    const uint32_t sb = smem_u32(sh);

    const int t    = threadIdx.x;
    const int lane = t & 31;
    const int wid  = t >> 5;
    const int sub  = lane >> 3;
    const int l7   = lane & 7;
    const int g    = lane >> 2;
    const int c2   = (lane & 3) * 2;

    const int q0 = blockIdx.x * 128;
    const int bh = blockIdx.y;
    const int b  = bh >> 4;
    const int h  = bh & 15;

    const size_t base = (size_t)b * SEQ * DM + h * DEPTH;
    const __half* Qhb = g_Qh + base;
    const __half* Khb = g_Kh + base;
    const __half* Vhb = g_Vh + base;

    // ---- stage Q tile (128 rows x 64), read fragments to regs ----
    #pragma unroll
    for (int j = 0; j < 4; j++) {
        const int r = t + j * 256;            // 0..1023
        const int row = r >> 3, c16 = r & 7;
        const __half* src = Qhb + (size_t)(q0 + row) * DM + c16 * 8;
        __half* dst = sh + (row >> 6) * AT_H + (row & 63) * ASKP + c16 * 8;
        *(uint4*)dst = *(const uint4*)src;
    }
    __syncthreads();

    uint32_t qh[4][4];
    {
        const int qrow = wid * 16 + (l7 | ((sub & 1) << 3));
        const uint32_t hb = sb + ((qrow >> 6) * AT_H + (qrow & 63) * ASKP) * 2;
        #pragma unroll
        for (int kk = 0; kk < 4; kk++)
            ldm_x4(qh[kk], hb + (((sub >> 1) << 3) + kk * 16) * 2);
    }
    __syncthreads();   // Q in regs before chunk-0 prefetch overwrites stage 0

    float oacc[8][4];
    #pragma unroll
    for (int j = 0; j < 8; j++)
        #pragma unroll
        for (int c = 0; c < 4; c++) oacc[j][c] = 0.f;
    float rmax[2] = {-1e30f, -1e30f};
    float rsum[2] = {0.f, 0.f};

    const int mrow = q0 + wid * 16 + g;

    attn_issue(sb, 0, 0, Khb, Vhb, t);
    attn_issue(sb, 1, ATK, Khb, Vhb, t);

    // fragment smem offsets (within a stage)
    const uint32_t s_off = ((l7 + ((sub >> 1) << 3)) * ASKP
                            + ((sub & 1) << 3)) * 2;        // K frag base
    const uint32_t v_off = ((((sub & 1) << 3) + l7) * ASKP
                            + ((sub >> 1) << 3)) * 2;       // V frag base

    const int NC = SEQ / ATK;   // 16
    for (int kc = 0; kc < NC; kc++) {
        const int k0 = kc * ATK;
        if (kc + 1 < NC) CP_WAIT1(); else CP_WAIT0();
        __syncthreads();
        if (kc + 2 < NC)
            attn_issue(sb, (kc + 2) % 3, (kc + 2) * ATK, Khb, Vhb, t);

        const uint32_t stb  = sb + (kc % 3) * (ASTAGE_H * 2);
        const uint32_t bKh2 = stb;
        const uint32_t bVh2 = stb + AT_H * 2;

        // ---- S = Qh K^T : 16 groups (kk outer, jp inner), prefetch 1 ahead
        float sacc[8][4];
        #pragma unroll
        for (int j = 0; j < 8; j++)
            #pragma unroll
            for (int c = 0; c < 4; c++) sacc[j][c] = 0.f;

        uint32_t rh[2][4];
        ldm_x4(rh[0], bKh2 + s_off);   // g=0: kk=0, jp=0
        #pragma unroll
        for (int gi = 0; gi < 16; gi++) {
            const int kk = gi >> 2, jp = gi & 3;
            const int cur = gi & 1;
            if (gi < 15) {
                const int gn = gi + 1;
                ldm_x4(rh[cur ^ 1],
                       bKh2 + s_off + ((gn & 3) * 16 * ASKP + (gn >> 2) * 16) * 2);
            }
            mma16816(sacc[2 * jp],     qh[kk], rh[cur]);
            mma16816(sacc[2 * jp + 1], qh[kk], rh[cur] + 2);
        }

        // ---- mask ----
        #pragma unroll
        for (int j = 0; j < 8; j++) {
            int col = k0 + j * 8 + c2;
            float2 m0 = *(const float2*)(mask + (size_t)mrow * SEQ + col);
            float2 m1 = *(const float2*)(mask + (size_t)(mrow + 8) * SEQ + col);
            sacc[j][0] -= 1e9f * m0.x; sacc[j][1] -= 1e9f * m0.y;
            sacc[j][2] -= 1e9f * m1.x; sacc[j][3] -= 1e9f * m1.y;
        }

        // ---- online softmax ----
        #pragma unroll
        for (int r = 0; r < 2; r++) {
            float mx = -1e30f;
            #pragma unroll
            for (int j = 0; j < 8; j++)
                mx = fmaxf(mx, fmaxf(sacc[j][2 * r], sacc[j][2 * r + 1]));
            mx = fmaxf(mx, __shfl_xor_sync(0xffffffffu, mx, 1));
            mx = fmaxf(mx, __shfl_xor_sync(0xffffffffu, mx, 2));
            float nm   = fmaxf(rmax[r], mx);
            float corr = __expf(rmax[r] - nm);
            rmax[r] = nm;
            float ps = 0.f;
            #pragma unroll
            for (int j = 0; j < 8; j++) {
                float p0 = __expf(sacc[j][2 * r] - nm);
                float p1 = __expf(sacc[j][2 * r + 1] - nm);
                sacc[j][2 * r] = p0; sacc[j][2 * r + 1] = p1;
                ps += p0 + p1;
            }
            ps += __shfl_xor_sync(0xffffffffu, ps, 1);
            ps += __shfl_xor_sync(0xffffffffu, ps, 2);
            rsum[r] = rsum[r] * corr + ps;
            #pragma unroll
            for (int jn = 0; jn < 8; jn++) {
                oacc[jn][2 * r]     *= corr;
                oacc[jn][2 * r + 1] *= corr;
            }
        }

        // ---- O += P @ Vh : 16 groups (kk outer, jd inner), prefetch 1 ahead
        uint32_t vh[2][4], ph[4];
        ldm_x4_t(vh[0], bVh2 + v_off);  // g=0: kk=0, jd=0
        #pragma unroll
        for (int gi = 0; gi < 16; gi++) {
            const int kk = gi >> 2, jd = gi & 3;
            const int cur = gi & 1;
            if (jd == 0) {
                ph[0] = packh2(sacc[2 * kk][0],     sacc[2 * kk][1]);
                ph[1] = packh2(sacc[2 * kk][2],     sacc[2 * kk][3]);
                ph[2] = packh2(sacc[2 * kk + 1][0], sacc[2 * kk + 1][1]);
                ph[3] = packh2(sacc[2 * kk + 1][2], sacc[2 * kk + 1][3]);
            }
            if (gi < 15) {
                const int gn = gi + 1;
                ldm_x4_t(vh[cur ^ 1],
                         bVh2 + v_off + ((gn >> 2) * 16 * ASKP + (gn & 3) * 16) * 2);
            }
            mma16816(oacc[2 * jd],     ph, vh[cur]);
            mma16816(oacc[2 * jd + 1], ph, vh[cur] + 2);
        }
    }

    // ---- epilogue: normalize, write fp16 ----
    const float inv0 = 1.0f / rsum[0];
    const float inv1 = 1.0f / rsum[1];
    const int orow = q0 + wid * 16 + g;
    __half* Ohb = g_Oh + base + (size_t)orow * DM;
    #pragma unroll
    for (int jn = 0; jn < 8; jn++) {
        int cc = jn * 8 + c2;
        *(uint32_t*)(Ohb + cc) =
            packh2(oacc[jn][0] * inv0, oacc[jn][1] * inv0);
        *(uint32_t*)(Ohb + 8 * DM + cc) =
            packh2(oacc[jn][2] * inv1, oacc[jn][3] * inv1);
    }
}

// ---------------------------------------------------------------------------
extern "C" void kernel_launch(void* const* d_in, const int* in_sizes, int n_in,
                              void* d_out, int out_size)
{
    (void)in_sizes; (void)n_in; (void)out_size;
    const float* q    = (const float*)d_in[0];
    const float* k    = (const float*)d_in[1];
    const float* v    = (const float*)d_in[2];
    const float* mask = (const float*)d_in[3];
    const float* wq_w = (const float*)d_in[4];
    const float* wq_b = (const float*)d_in[5];
    const float* wk_w = (const float*)d_in[6];
    const float* wk_b = (const float*)d_in[7];
    const float* wv_w = (const float*)d_in[8];
    const float* wv_b = (const float*)d_in[9];
    const float* pl_w = (const float*)d_in[10];
    const float* pl_b = (const float*)d_in[11];
    float* out = (float*)d_out;

    __half *Qh, *Kh, *Vh, *Oh, *xq, *xk, *xv, *wq, *wk, *wv, *wp;
    cudaGetSymbolAddress((void**)&Qh, g_Qh);
    cudaGetSymbolAddress((void**)&Kh, g_Kh);
    cudaGetSymbolAddress((void**)&Vh, g_Vh);
    cudaGetSymbolAddress((void**)&Oh, g_Oh);
    cudaGetSymbolAddress((void**)&xq, g_xq);
    cudaGetSymbolAddress((void**)&xk, g_xk);
    cudaGetSymbolAddress((void**)&xv, g_xv);
    cudaGetSymbolAddress((void**)&wq, g_wq);
    cudaGetSymbolAddress((void**)&wk, g_wk);
    cudaGetSymbolAddress((void**)&wv, g_wv);
    cudaGetSymbolAddress((void**)&wp, g_wp);

    cudaFuncSetAttribute(gemm_qkv, cudaFuncAttributeMaxDynamicSharedMemorySize,
                         GEMM_SMEM);
    cudaFuncSetAttribute(gemm_out, cudaFuncAttributeMaxDynamicSharedMemorySize,
                         GEMM_SMEM);
    cudaFuncSetAttribute(attn_mma, cudaFuncAttributeMaxDynamicSharedMemorySize,
                         ATTN_SMEM);

    // all 7 conversions in one launch (depend only on inputs)
    conv_all<<<dim3(NX / 2048, 7), 256>>>(q, k, v, wq_w, wk_w, wv_w, pl_w,
                                          xq, xk, xv, wq, wk, wv, wp);

    // Q/K/V projections batched (1/sqrt(64) folded into Q inside kernel)
    gemm_qkv<<<dim3(DM / BN, MROWS / BM, 3), 256, GEMM_SMEM>>>(
        xq, xk, xv, wq, wk, wv, wq_b, wk_b, wv_b, Qh, Kh, Vh);

    // attention
    attn_mma<<<dim3(SEQ / 128, BATCH * NHEAD), 256, ATTN_SMEM>>>(mask);

    // output projection (fp32 out)
    gemm_out<<<dim3(DM / BN, MROWS / BM), 256, GEMM_SMEM>>>(Oh, wp, pl_b, out);
}